// round 1
// baseline (speedup 1.0000x reference)
#include <cuda_runtime.h>
#include <math.h>
#include <math_constants.h>

#define NN   50000
#define EE   300000
#define DIN  1024
#define HID  512
#define DOUT 30

// ---------------- scratch (no allocs allowed) ----------------
__device__ float g_h[(size_t)NN * HID];      // h = X @ W1
__device__ float g_acc1[(size_t)NN * HID];   // aggregation 1 accumulator -> h1
__device__ float g_gbuf[(size_t)NN * HID];   // g = h2 @ W2^T
__device__ float g_acc2[(size_t)NN * HID];   // aggregation 2 accumulator -> h3
__device__ float g_edge[EE];                 // edge score, then exp(score - max)
__device__ float g_m[NN];                    // segment max
__device__ float g_den[NN];                  // segment sum

// ---------------- init ----------------
__global__ void k_init(int n, long total) {
    long i = (long)blockIdx.x * blockDim.x + threadIdx.x;
    if (i < total) { g_acc1[i] = 0.f; g_acc2[i] = 0.f; }
    if (i < n)     { g_m[i] = -CUDART_INF_F; g_den[i] = 0.f; }
}

// ---------------- tiled SGEMM: C[M,N] = A[M,K] @ B[K,N] ----------------
// Requires N % 64 == 0 and K % 16 == 0 (true for all call sites). M guarded.
#define BM 64
#define BN 64
#define BK 16
__global__ __launch_bounds__(256) void k_sgemm(
    const float* __restrict__ A, const float* __restrict__ B,
    float* __restrict__ C, int M, int N, int K)
{
    __shared__ float As[BK][BM];
    __shared__ float Bs[BK][BN];
    const int tid = threadIdx.y * 16 + threadIdx.x;
    const int brow = blockIdx.y * BM;
    const int bcol = blockIdx.x * BN;

    float acc[4][4];
    #pragma unroll
    for (int i = 0; i < 4; i++)
        #pragma unroll
        for (int j = 0; j < 4; j++) acc[i][j] = 0.f;

    const int aRow = tid >> 2, aCol = (tid & 3) * 4;
    const int bRow = tid >> 4, bCol = (tid & 15) * 4;

    for (int k0 = 0; k0 < K; k0 += BK) {
        float4 av = make_float4(0.f, 0.f, 0.f, 0.f);
        int gr = brow + aRow;
        if (gr < M) av = *(const float4*)(A + (size_t)gr * K + k0 + aCol);
        As[aCol + 0][aRow] = av.x;
        As[aCol + 1][aRow] = av.y;
        As[aCol + 2][aRow] = av.z;
        As[aCol + 3][aRow] = av.w;

        float4 bv = *(const float4*)(B + (size_t)(k0 + bRow) * N + bcol + bCol);
        *(float4*)&Bs[bRow][bCol] = bv;
        __syncthreads();

        #pragma unroll
        for (int k = 0; k < BK; k++) {
            float4 a4 = *(const float4*)&As[k][threadIdx.y * 4];
            float4 b4 = *(const float4*)&Bs[k][threadIdx.x * 4];
            float a[4] = {a4.x, a4.y, a4.z, a4.w};
            float b[4] = {b4.x, b4.y, b4.z, b4.w};
            #pragma unroll
            for (int i = 0; i < 4; i++)
                #pragma unroll
                for (int j = 0; j < 4; j++) acc[i][j] = fmaf(a[i], b[j], acc[i][j]);
        }
        __syncthreads();
    }

    #pragma unroll
    for (int i = 0; i < 4; i++) {
        int row = brow + threadIdx.y * 4 + i;
        if (row < M) {
            float* cp = C + (size_t)row * N + bcol + threadIdx.x * 4;
            cp[0] = acc[i][0]; cp[1] = acc[i][1]; cp[2] = acc[i][2]; cp[3] = acc[i][3];
        }
    }
}

// ---------------- edge scores: e = att . leaky_relu(h[src]+h[dst]) ----------------
__global__ void k_score(const int* __restrict__ src, const int* __restrict__ dst,
                        const float* __restrict__ att, int E)
{
    int w = blockIdx.x * 8 + threadIdx.y;
    if (w >= E) return;
    int lane = threadIdx.x;
    const float4* hs = (const float4*)(g_h + (size_t)src[w] * HID);
    const float4* hd = (const float4*)(g_h + (size_t)dst[w] * HID);
    const float4* at = (const float4*)att;
    float s = 0.f;
    #pragma unroll
    for (int it = 0; it < HID / 128; it++) {
        int idx = it * 32 + lane;
        float4 a = hs[idx], b = hd[idx], c = __ldg(&at[idx]);
        float v;
        v = a.x + b.x; v = v > 0.f ? v : 0.2f * v; s = fmaf(v, c.x, s);
        v = a.y + b.y; v = v > 0.f ? v : 0.2f * v; s = fmaf(v, c.y, s);
        v = a.z + b.z; v = v > 0.f ? v : 0.2f * v; s = fmaf(v, c.z, s);
        v = a.w + b.w; v = v > 0.f ? v : 0.2f * v; s = fmaf(v, c.w, s);
    }
    #pragma unroll
    for (int o = 16; o; o >>= 1) s += __shfl_xor_sync(0xffffffffu, s, o);
    if (lane == 0) g_edge[w] = s;
}

// ---------------- segment max (atomic float max via int punning) ----------------
__device__ __forceinline__ void atomicMaxF(float* addr, float v) {
    if (v >= 0.f) atomicMax((int*)addr, __float_as_int(v));
    else          atomicMin((unsigned int*)addr, __float_as_uint(v));
}

__global__ void k_max(const int* __restrict__ dst, int E) {
    int e = blockIdx.x * 256 + threadIdx.x;
    if (e < E) atomicMaxF(&g_m[dst[e]], g_edge[e]);
}

// ---------------- exp + segment sum ----------------
__global__ void k_exp(const int* __restrict__ dst, int E) {
    int e = blockIdx.x * 256 + threadIdx.x;
    if (e >= E) return;
    int d = dst[e];
    float ex = expf(g_edge[e] - g_m[d]);
    g_edge[e] = ex;
    atomicAdd(&g_den[d], ex);
}

// ---------------- weighted scatter-add aggregation ----------------
__global__ void k_agg(const float* __restrict__ in, float* __restrict__ out,
                      const int* __restrict__ src, const int* __restrict__ dst, int E)
{
    int w = blockIdx.x * 8 + threadIdx.y;
    if (w >= E) return;
    int lane = threadIdx.x;
    int d = dst[w];
    float wgt = g_edge[w] / g_den[d];
    const float4* ip = (const float4*)(in + (size_t)src[w] * HID);
    float* op = out + (size_t)d * HID;
    #pragma unroll
    for (int it = 0; it < HID / 128; it++) {
        int idx = it * 32 + lane;
        float4 v = ip[idx];
        int base = idx * 4;
        atomicAdd(op + base + 0, wgt * v.x);
        atomicAdd(op + base + 1, wgt * v.y);
        atomicAdd(op + base + 2, wgt * v.z);
        atomicAdd(op + base + 3, wgt * v.w);
    }
}

// ---------------- ELU in place ----------------
__global__ void k_elu(float* __restrict__ x, long total) {
    long i = (long)blockIdx.x * 256 + threadIdx.x;
    if (i < total) {
        float v = x[i];
        x[i] = v > 0.f ? v : expm1f(v);
    }
}

// ---------------- h2 = h1 @ W2  (K=512, OUT=30), one warp per row ----------------
__global__ void k_h2(const float* __restrict__ h1, const float* __restrict__ W2,
                     float* __restrict__ h2, int n)
{
    int w = blockIdx.x * 8 + threadIdx.y;
    if (w >= n) return;
    int lane = threadIdx.x;
    float acc[DOUT];
    #pragma unroll
    for (int j = 0; j < DOUT; j++) acc[j] = 0.f;
    const float* row = h1 + (size_t)w * HID;
    for (int k = lane; k < HID; k += 32) {
        float hv = row[k];
        const float* w2r = W2 + (size_t)k * DOUT;
        #pragma unroll
        for (int j = 0; j < DOUT; j++) acc[j] = fmaf(hv, __ldg(&w2r[j]), acc[j]);
    }
    #pragma unroll
    for (int j = 0; j < DOUT; j++)
        #pragma unroll
        for (int o = 16; o; o >>= 1) acc[j] += __shfl_xor_sync(0xffffffffu, acc[j], o);
    #pragma unroll
    for (int j = 0; j < DOUT; j++)
        if (lane == j) h2[(size_t)w * DOUT + j] = acc[j];
}

// ---------------- g = h2 @ W2^T  (K=30), one thread per output ----------------
__global__ void k_g(const float* __restrict__ h2, const float* __restrict__ W2, long total) {
    long i = (long)blockIdx.x * 256 + threadIdx.x;
    if (i >= total) return;
    int nrow = (int)(i / HID);
    int c = (int)(i % HID);
    const float* h2r = h2 + (size_t)nrow * DOUT;
    const float* w2r = W2 + (size_t)c * DOUT;
    float s = 0.f;
    #pragma unroll
    for (int j = 0; j < DOUT; j++) s = fmaf(h2r[j], __ldg(&w2r[j]), s);
    g_gbuf[i] = s;
}

// ---------------- launch ----------------
extern "C" void kernel_launch(void* const* d_in, const int* in_sizes, int n_in,
                              void* d_out, int out_size)
{
    const float* features = (const float*)d_in[0];
    const int*   eidx     = (const int*)d_in[1];
    const float* W1       = (const float*)d_in[2];
    const float* att1     = (const float*)d_in[3];
    const float* W2       = (const float*)d_in[4];
    const float* W4       = (const float*)d_in[5];
    float* out = (float*)d_out;

    const int n = in_sizes[0] / DIN;      // 50000
    const int E = in_sizes[1] / 2;        // 300000
    const int* src = eidx;
    const int* dst = eidx + E;

    float* h;   cudaGetSymbolAddress((void**)&h,   g_h);
    float* a1;  cudaGetSymbolAddress((void**)&a1,  g_acc1);
    float* gb;  cudaGetSymbolAddress((void**)&gb,  g_gbuf);
    float* a2;  cudaGetSymbolAddress((void**)&a2,  g_acc2);

    const long tot = (long)n * HID;
    const dim3 warp8(32, 8);
    const int eblk = (E + 7) / 8;

    // 0) init accumulators / softmax state
    k_init<<<(unsigned)((tot + 255) / 256), 256>>>(n, tot);

    // 1) h = X @ W1   [50000,1024]@[1024,512]
    {
        dim3 g(HID / BN, (n + BM - 1) / BM), b(16, 16);
        k_sgemm<<<g, b>>>(features, W1, h, n, HID, DIN);
    }

    // 2) edge scores
    k_score<<<eblk, warp8>>>(src, dst, att1, E);

    // 3) segment softmax
    k_max<<<(E + 255) / 256, 256>>>(dst, E);
    k_exp<<<(E + 255) / 256, 256>>>(dst, E);

    // 4) h1 = elu(aggregate(h))
    k_agg<<<eblk, warp8>>>(h, a1, src, dst, E);
    k_elu<<<(unsigned)((tot + 255) / 256), 256>>>(a1, tot);

    // 5) h2 = h1 @ W2 -> first output chunk [n, 30]
    k_h2<<<(n + 7) / 8, warp8>>>(a1, W2, out, n);

    // 6) g = h2 @ W2^T
    k_g<<<(unsigned)((tot + 255) / 256), 256>>>(out, W2, tot);

    // 7) h3 = elu(aggregate(g))
    k_agg<<<eblk, warp8>>>(gb, a2, src, dst, E);
    k_elu<<<(unsigned)((tot + 255) / 256), 256>>>(a2, tot);

    // 8) h4 = h3 @ W4 -> second output chunk [n, 1024]
    {
        dim3 g(DIN / BN, (n + BM - 1) / BM), b(16, 16);
        k_sgemm<<<g, b>>>(a2, W4, out + (size_t)n * DOUT, n, DIN, HID);
    }
}

// round 2
// speedup vs baseline: 1.5526x; 1.5526x over previous
#include <cuda_runtime.h>
#include <cuda_bf16.h>
#include <math.h>
#include <math_constants.h>
#include <stdint.h>

#define NN   50000
#define EE   300000
#define DIN  1024
#define HID  512
#define DOUT 30

// ---------------- scratch (no allocs allowed) ----------------
__device__ float g_h[(size_t)NN * HID];      // h = X @ W1
__device__ float g_acc1[(size_t)NN * HID];   // aggregation 1 accumulator -> h1
__device__ float g_gbuf[(size_t)NN * HID];   // g = h2 @ W2^T
__device__ float g_acc2[(size_t)NN * HID];   // aggregation 2 accumulator -> h3
__device__ float g_edge[EE];                 // edge score, then exp(score - max)
__device__ float g_m[NN];                    // segment max
__device__ float g_den[NN];                  // segment sum

// ---------------- init ----------------
__global__ void k_init(int n, long total) {
    long i = (long)blockIdx.x * blockDim.x + threadIdx.x;
    if (i < total) { g_acc1[i] = 0.f; g_acc2[i] = 0.f; }
    if (i < n)     { g_m[i] = -CUDART_INF_F; g_den[i] = 0.f; }
}

// ================= tensor-core GEMM: C[M,N] = A[M,K] @ B[K,N] =================
// fp32 in/out, internally bf16 hi/lo split (3 mma products) for ~1e-5 accuracy.
// Requires N % 128 == 0, K % 32 == 0. M guarded.

__device__ __forceinline__ void ldm_x4(uint32_t* r, uint32_t addr) {
    asm volatile("ldmatrix.sync.aligned.m8n8.x4.shared.b16 {%0,%1,%2,%3}, [%4];"
        : "=r"(r[0]), "=r"(r[1]), "=r"(r[2]), "=r"(r[3]) : "r"(addr));
}
__device__ __forceinline__ void ldm_x2t(uint32_t* r, uint32_t addr) {
    asm volatile("ldmatrix.sync.aligned.m8n8.x2.trans.shared.b16 {%0,%1}, [%2];"
        : "=r"(r[0]), "=r"(r[1]) : "r"(addr));
}
__device__ __forceinline__ void mma16816(float* c, const uint32_t* a, const uint32_t* b) {
    asm volatile("mma.sync.aligned.m16n8k16.row.col.f32.bf16.bf16.f32 "
        "{%0,%1,%2,%3}, {%4,%5,%6,%7}, {%8,%9}, {%0,%1,%2,%3};"
        : "+f"(c[0]), "+f"(c[1]), "+f"(c[2]), "+f"(c[3])
        : "r"(a[0]), "r"(a[1]), "r"(a[2]), "r"(a[3]), "r"(b[0]), "r"(b[1]));
}

// split fp32 -> bf16 hi + bf16 lo
__device__ __forceinline__ void split2(float x, __nv_bfloat16& h, __nv_bfloat16& l) {
    h = __float2bfloat16(x);
    l = __float2bfloat16(x - __bfloat162float(h));
}

#define APAD 8    // As row stride = 40 bf16 (80 B) -> conflict-free ldmatrix
#define BPAD 8    // Bs row stride = 136 bf16 (272 B)

__global__ __launch_bounds__(256) void k_mma_split(
    const float* __restrict__ A, const float* __restrict__ B,
    float* __restrict__ C, int M, int N, int K)
{
    __shared__ __nv_bfloat16 As[2][128][32 + APAD];
    __shared__ __nv_bfloat16 Bs[2][32][128 + BPAD];

    const int tid  = threadIdx.x;
    const int lane = tid & 31;
    const int wid  = tid >> 5;
    const int wm   = (wid & 1) * 64;   // warp M offset within CTA tile
    const int wn   = (wid >> 1) * 32;  // warp N offset
    const int bm   = blockIdx.y * 128;
    const int bn   = blockIdx.x * 128;

    float acc[4][4][4] = {};

    for (int k0 = 0; k0 < K; k0 += 32) {
        // ---- load A tile (128 x 32 fp32), split to hi/lo bf16 ----
        #pragma unroll
        for (int i = 0; i < 4; i++) {
            int idx = tid + i * 256;          // 0..1023 float4 slots
            int r  = idx >> 3;                // 128 rows
            int c4 = (idx & 7) * 4;           // 8 float4 per row
            float4 v = make_float4(0.f, 0.f, 0.f, 0.f);
            if (bm + r < M) v = *(const float4*)(A + (size_t)(bm + r) * K + k0 + c4);
            union { __nv_bfloat16 b[4]; uint2 u; } ph, pl;
            split2(v.x, ph.b[0], pl.b[0]); split2(v.y, ph.b[1], pl.b[1]);
            split2(v.z, ph.b[2], pl.b[2]); split2(v.w, ph.b[3], pl.b[3]);
            *(uint2*)&As[0][r][c4] = ph.u;
            *(uint2*)&As[1][r][c4] = pl.u;
        }
        // ---- load B tile (32 x 128 fp32), split ----
        #pragma unroll
        for (int i = 0; i < 4; i++) {
            int idx = tid + i * 256;
            int r  = idx >> 5;                // 32 rows
            int c4 = (idx & 31) * 4;          // 32 float4 per row
            float4 v = *(const float4*)(B + (size_t)(k0 + r) * N + bn + c4);
            union { __nv_bfloat16 b[4]; uint2 u; } ph, pl;
            split2(v.x, ph.b[0], pl.b[0]); split2(v.y, ph.b[1], pl.b[1]);
            split2(v.z, ph.b[2], pl.b[2]); split2(v.w, ph.b[3], pl.b[3]);
            *(uint2*)&Bs[0][r][c4] = ph.u;
            *(uint2*)&Bs[1][r][c4] = pl.u;
        }
        __syncthreads();

        #pragma unroll
        for (int ks = 0; ks < 2; ks++) {
            uint32_t ah[4][4], al[4][4], bh[4][2], bl[4][2];
            #pragma unroll
            for (int mf = 0; mf < 4; mf++) {
                int rr = wm + mf * 16 + (lane & 15);
                int cc = ks * 16 + (lane >> 4) * 8;
                ldm_x4(ah[mf], (uint32_t)__cvta_generic_to_shared(&As[0][rr][cc]));
                ldm_x4(al[mf], (uint32_t)__cvta_generic_to_shared(&As[1][rr][cc]));
            }
            #pragma unroll
            for (int nf = 0; nf < 4; nf++) {
                int rr = ks * 16 + (lane & 15);
                int cc = wn + nf * 8;
                ldm_x2t(bh[nf], (uint32_t)__cvta_generic_to_shared(&Bs[0][rr][cc]));
                ldm_x2t(bl[nf], (uint32_t)__cvta_generic_to_shared(&Bs[1][rr][cc]));
            }
            #pragma unroll
            for (int mf = 0; mf < 4; mf++)
                #pragma unroll
                for (int nf = 0; nf < 4; nf++) {
                    mma16816(acc[mf][nf], ah[mf], bh[nf]);  // hi*hi
                    mma16816(acc[mf][nf], ah[mf], bl[nf]);  // hi*lo
                    mma16816(acc[mf][nf], al[mf], bh[nf]);  // lo*hi
                }
        }
        __syncthreads();
    }

    // ---- epilogue ----
    #pragma unroll
    for (int mf = 0; mf < 4; mf++) {
        int r0 = bm + wm + mf * 16 + (lane >> 2);
        #pragma unroll
        for (int nf = 0; nf < 4; nf++) {
            int c = bn + wn + nf * 8 + (lane & 3) * 2;
            if (r0 < M) {
                C[(size_t)r0 * N + c]     = acc[mf][nf][0];
                C[(size_t)r0 * N + c + 1] = acc[mf][nf][1];
            }
            if (r0 + 8 < M) {
                C[(size_t)(r0 + 8) * N + c]     = acc[mf][nf][2];
                C[(size_t)(r0 + 8) * N + c + 1] = acc[mf][nf][3];
            }
        }
    }
}

// ---------------- edge scores: e = att . leaky_relu(h[src]+h[dst]) ----------------
__global__ void k_score(const int* __restrict__ src, const int* __restrict__ dst,
                        const float* __restrict__ att, int E)
{
    int w = blockIdx.x * 8 + threadIdx.y;
    if (w >= E) return;
    int lane = threadIdx.x;
    const float4* hs = (const float4*)(g_h + (size_t)src[w] * HID);
    const float4* hd = (const float4*)(g_h + (size_t)dst[w] * HID);
    const float4* at = (const float4*)att;
    float s = 0.f;
    #pragma unroll
    for (int it = 0; it < HID / 128; it++) {
        int idx = it * 32 + lane;
        float4 a = hs[idx], b = hd[idx], c = __ldg(&at[idx]);
        float v;
        v = a.x + b.x; v = v > 0.f ? v : 0.2f * v; s = fmaf(v, c.x, s);
        v = a.y + b.y; v = v > 0.f ? v : 0.2f * v; s = fmaf(v, c.y, s);
        v = a.z + b.z; v = v > 0.f ? v : 0.2f * v; s = fmaf(v, c.z, s);
        v = a.w + b.w; v = v > 0.f ? v : 0.2f * v; s = fmaf(v, c.w, s);
    }
    #pragma unroll
    for (int o = 16; o; o >>= 1) s += __shfl_xor_sync(0xffffffffu, s, o);
    if (lane == 0) g_edge[w] = s;
}

// ---------------- segment max (atomic float max via int punning) ----------------
__device__ __forceinline__ void atomicMaxF(float* addr, float v) {
    if (v >= 0.f) atomicMax((int*)addr, __float_as_int(v));
    else          atomicMin((unsigned int*)addr, __float_as_uint(v));
}

__global__ void k_max(const int* __restrict__ dst, int E) {
    int e = blockIdx.x * 256 + threadIdx.x;
    if (e < E) atomicMaxF(&g_m[dst[e]], g_edge[e]);
}

// ---------------- exp + segment sum ----------------
__global__ void k_exp(const int* __restrict__ dst, int E) {
    int e = blockIdx.x * 256 + threadIdx.x;
    if (e >= E) return;
    int d = dst[e];
    float ex = expf(g_edge[e] - g_m[d]);
    g_edge[e] = ex;
    atomicAdd(&g_den[d], ex);
}

// ---------------- weighted scatter-add aggregation ----------------
__global__ void k_agg(const float* __restrict__ in, float* __restrict__ out,
                      const int* __restrict__ src, const int* __restrict__ dst, int E)
{
    int w = blockIdx.x * 8 + threadIdx.y;
    if (w >= E) return;
    int lane = threadIdx.x;
    int d = dst[w];
    float wgt = g_edge[w] / g_den[d];
    const float4* ip = (const float4*)(in + (size_t)src[w] * HID);
    float* op = out + (size_t)d * HID;
    #pragma unroll
    for (int it = 0; it < HID / 128; it++) {
        int idx = it * 32 + lane;
        float4 v = ip[idx];
        int base = idx * 4;
        atomicAdd(op + base + 0, wgt * v.x);
        atomicAdd(op + base + 1, wgt * v.y);
        atomicAdd(op + base + 2, wgt * v.z);
        atomicAdd(op + base + 3, wgt * v.w);
    }
}

// ---------------- ELU in place ----------------
__global__ void k_elu(float* __restrict__ x, long total) {
    long i = (long)blockIdx.x * 256 + threadIdx.x;
    if (i < total) {
        float v = x[i];
        x[i] = v > 0.f ? v : expm1f(v);
    }
}

// ---------------- h2 = h1 @ W2  (K=512, OUT=30), one warp per row ----------------
__global__ void k_h2(const float* __restrict__ h1, const float* __restrict__ W2,
                     float* __restrict__ h2, int n)
{
    int w = blockIdx.x * 8 + threadIdx.y;
    if (w >= n) return;
    int lane = threadIdx.x;
    float acc[DOUT];
    #pragma unroll
    for (int j = 0; j < DOUT; j++) acc[j] = 0.f;
    const float* row = h1 + (size_t)w * HID;
    for (int k = lane; k < HID; k += 32) {
        float hv = row[k];
        const float* w2r = W2 + (size_t)k * DOUT;
        #pragma unroll
        for (int j = 0; j < DOUT; j++) acc[j] = fmaf(hv, __ldg(&w2r[j]), acc[j]);
    }
    #pragma unroll
    for (int j = 0; j < DOUT; j++)
        #pragma unroll
        for (int o = 16; o; o >>= 1) acc[j] += __shfl_xor_sync(0xffffffffu, acc[j], o);
    #pragma unroll
    for (int j = 0; j < DOUT; j++)
        if (lane == j) h2[(size_t)w * DOUT + j] = acc[j];
}

// ---------------- g = h2 @ W2^T  (K=30), one thread per output ----------------
__global__ void k_g(const float* __restrict__ h2, const float* __restrict__ W2, long total) {
    long i = (long)blockIdx.x * 256 + threadIdx.x;
    if (i >= total) return;
    int nrow = (int)(i / HID);
    int c = (int)(i % HID);
    const float* h2r = h2 + (size_t)nrow * DOUT;
    const float* w2r = W2 + (size_t)c * DOUT;
    float s = 0.f;
    #pragma unroll
    for (int j = 0; j < DOUT; j++) s = fmaf(h2r[j], __ldg(&w2r[j]), s);
    g_gbuf[i] = s;
}

// ---------------- launch ----------------
extern "C" void kernel_launch(void* const* d_in, const int* in_sizes, int n_in,
                              void* d_out, int out_size)
{
    const float* features = (const float*)d_in[0];
    const int*   eidx     = (const int*)d_in[1];
    const float* W1       = (const float*)d_in[2];
    const float* att1     = (const float*)d_in[3];
    const float* W2       = (const float*)d_in[4];
    const float* W4       = (const float*)d_in[5];
    float* out = (float*)d_out;

    const int n = in_sizes[0] / DIN;      // 50000
    const int E = in_sizes[1] / 2;        // 300000
    const int* src = eidx;
    const int* dst = eidx + E;

    float* h;   cudaGetSymbolAddress((void**)&h,   g_h);
    float* a1;  cudaGetSymbolAddress((void**)&a1,  g_acc1);
    float* gb;  cudaGetSymbolAddress((void**)&gb,  g_gbuf);
    float* a2;  cudaGetSymbolAddress((void**)&a2,  g_acc2);

    const long tot = (long)n * HID;
    const dim3 warp8(32, 8);
    const int eblk = (E + 7) / 8;

    // 0) init accumulators / softmax state
    k_init<<<(unsigned)((tot + 255) / 256), 256>>>(n, tot);

    // 1) h = X @ W1   [50000,1024]@[1024,512]  (tensor cores, bf16 split)
    {
        dim3 g(HID / 128, (n + 127) / 128);
        k_mma_split<<<g, 256>>>(features, W1, h, n, HID, DIN);
    }

    // 2) edge scores
    k_score<<<eblk, warp8>>>(src, dst, att1, E);

    // 3) segment softmax
    k_max<<<(E + 255) / 256, 256>>>(dst, E);
    k_exp<<<(E + 255) / 256, 256>>>(dst, E);

    // 4) h1 = elu(aggregate(h))
    k_agg<<<eblk, warp8>>>(h, a1, src, dst, E);
    k_elu<<<(unsigned)((tot + 255) / 256), 256>>>(a1, tot);

    // 5) h2 = h1 @ W2 -> first output chunk [n, 30]
    k_h2<<<(n + 7) / 8, warp8>>>(a1, W2, out, n);

    // 6) g = h2 @ W2^T
    k_g<<<(unsigned)((tot + 255) / 256), 256>>>(out, W2, tot);

    // 7) h3 = elu(aggregate(g))
    k_agg<<<eblk, warp8>>>(gb, a2, src, dst, E);
    k_elu<<<(unsigned)((tot + 255) / 256), 256>>>(a2, tot);

    // 8) h4 = h3 @ W4 -> second output chunk [n, 1024]  (tensor cores)
    {
        dim3 g(DIN / 128, (n + 127) / 128);
        k_mma_split<<<g, 256>>>(a2, W4, out + (size_t)n * DOUT, n, DIN, HID);
    }
}

// round 3
// speedup vs baseline: 1.9851x; 1.2785x over previous
#include <cuda_runtime.h>
#include <cuda_bf16.h>
#include <math.h>
#include <math_constants.h>
#include <stdint.h>

#define NN   50000
#define EE   300000
#define DIN  1024
#define HID  512
#define DOUT 30

// ---------------- scratch (no allocs allowed) ----------------
__device__ float g_h[(size_t)NN * HID];      // h = X @ W1
__device__ float g_h1[(size_t)NN * HID];     // h1 = elu(agg1)
__device__ float g_gbuf[(size_t)NN * HID];   // g = h2 @ W2^T
__device__ float g_h3[(size_t)NN * HID];     // h3 = elu(agg2)
__device__ int   g_cnt[NN];                  // per-dst degree
__device__ int   g_rowptr[NN + 1];           // CSR row pointers
__device__ int   g_cur[NN];                  // scatter cursors
__device__ int   g_csrc[EE];                 // CSR src node ids
__device__ float g_w[EE];                    // raw score, then normalized weight

// ---------------- CSR build ----------------
__global__ void k_zero_cnt(int n) {
    int i = blockIdx.x * 256 + threadIdx.x;
    if (i < n) g_cnt[i] = 0;
}

__global__ void k_hist(const int* __restrict__ dst, int E) {
    int e = blockIdx.x * 256 + threadIdx.x;
    if (e < E) atomicAdd(&g_cnt[dst[e]], 1);
}

__global__ __launch_bounds__(1024) void k_scan(int n, int E) {
    __shared__ int sums[1024];
    int t = threadIdx.x;
    int chunk = (n + 1023) >> 10;
    int s0 = t * chunk, s1 = min(s0 + chunk, n);
    int local = 0;
    for (int i = s0; i < s1; i++) local += g_cnt[i];
    sums[t] = local;
    __syncthreads();
    #pragma unroll
    for (int off = 1; off < 1024; off <<= 1) {
        int x = (t >= off) ? sums[t - off] : 0;
        __syncthreads();
        sums[t] += x;
        __syncthreads();
    }
    int run = sums[t] - local;   // exclusive prefix
    for (int i = s0; i < s1; i++) {
        int c = g_cnt[i];
        g_rowptr[i] = run;
        g_cur[i] = run;
        run += c;
    }
    if (t == 0) g_rowptr[n] = E;
}

__global__ void k_scatter(const int* __restrict__ src, const int* __restrict__ dst, int E) {
    int e = blockIdx.x * 256 + threadIdx.x;
    if (e >= E) return;
    int pos = atomicAdd(&g_cur[dst[e]], 1);
    g_csrc[pos] = src[e];
}

// ================= tensor-core GEMM: C[M,N] = A[M,K] @ B[K,N] =================
// fp32 in/out, internally bf16 hi/lo split (3 mma products) for ~1e-5 accuracy.

__device__ __forceinline__ void ldm_x4(uint32_t* r, uint32_t addr) {
    asm volatile("ldmatrix.sync.aligned.m8n8.x4.shared.b16 {%0,%1,%2,%3}, [%4];"
        : "=r"(r[0]), "=r"(r[1]), "=r"(r[2]), "=r"(r[3]) : "r"(addr));
}
__device__ __forceinline__ void ldm_x2t(uint32_t* r, uint32_t addr) {
    asm volatile("ldmatrix.sync.aligned.m8n8.x2.trans.shared.b16 {%0,%1}, [%2];"
        : "=r"(r[0]), "=r"(r[1]) : "r"(addr));
}
__device__ __forceinline__ void mma16816(float* c, const uint32_t* a, const uint32_t* b) {
    asm volatile("mma.sync.aligned.m16n8k16.row.col.f32.bf16.bf16.f32 "
        "{%0,%1,%2,%3}, {%4,%5,%6,%7}, {%8,%9}, {%0,%1,%2,%3};"
        : "+f"(c[0]), "+f"(c[1]), "+f"(c[2]), "+f"(c[3])
        : "r"(a[0]), "r"(a[1]), "r"(a[2]), "r"(a[3]), "r"(b[0]), "r"(b[1]));
}
__device__ __forceinline__ void split2(float x, __nv_bfloat16& h, __nv_bfloat16& l) {
    h = __float2bfloat16(x);
    l = __float2bfloat16(x - __bfloat162float(h));
}

#define APAD 8
#define BPAD 8

__global__ __launch_bounds__(256) void k_mma_split(
    const float* __restrict__ A, const float* __restrict__ B,
    float* __restrict__ C, int M, int N, int K)
{
    __shared__ __nv_bfloat16 As[2][128][32 + APAD];
    __shared__ __nv_bfloat16 Bs[2][32][128 + BPAD];

    const int tid  = threadIdx.x;
    const int lane = tid & 31;
    const int wid  = tid >> 5;
    const int wm   = (wid & 1) * 64;
    const int wn   = (wid >> 1) * 32;
    const int bm   = blockIdx.y * 128;
    const int bn   = blockIdx.x * 128;

    float acc[4][4][4] = {};

    for (int k0 = 0; k0 < K; k0 += 32) {
        #pragma unroll
        for (int i = 0; i < 4; i++) {
            int idx = tid + i * 256;
            int r  = idx >> 3;
            int c4 = (idx & 7) * 4;
            float4 v = make_float4(0.f, 0.f, 0.f, 0.f);
            if (bm + r < M) v = *(const float4*)(A + (size_t)(bm + r) * K + k0 + c4);
            union { __nv_bfloat16 b[4]; uint2 u; } ph, pl;
            split2(v.x, ph.b[0], pl.b[0]); split2(v.y, ph.b[1], pl.b[1]);
            split2(v.z, ph.b[2], pl.b[2]); split2(v.w, ph.b[3], pl.b[3]);
            *(uint2*)&As[0][r][c4] = ph.u;
            *(uint2*)&As[1][r][c4] = pl.u;
        }
        #pragma unroll
        for (int i = 0; i < 4; i++) {
            int idx = tid + i * 256;
            int r  = idx >> 5;
            int c4 = (idx & 31) * 4;
            float4 v = *(const float4*)(B + (size_t)(k0 + r) * N + bn + c4);
            union { __nv_bfloat16 b[4]; uint2 u; } ph, pl;
            split2(v.x, ph.b[0], pl.b[0]); split2(v.y, ph.b[1], pl.b[1]);
            split2(v.z, ph.b[2], pl.b[2]); split2(v.w, ph.b[3], pl.b[3]);
            *(uint2*)&Bs[0][r][c4] = ph.u;
            *(uint2*)&Bs[1][r][c4] = pl.u;
        }
        __syncthreads();

        #pragma unroll
        for (int ks = 0; ks < 2; ks++) {
            uint32_t ah[4][4], al[4][4], bh[4][2], bl[4][2];
            #pragma unroll
            for (int mf = 0; mf < 4; mf++) {
                int rr = wm + mf * 16 + (lane & 15);
                int cc = ks * 16 + (lane >> 4) * 8;
                ldm_x4(ah[mf], (uint32_t)__cvta_generic_to_shared(&As[0][rr][cc]));
                ldm_x4(al[mf], (uint32_t)__cvta_generic_to_shared(&As[1][rr][cc]));
            }
            #pragma unroll
            for (int nf = 0; nf < 4; nf++) {
                int rr = ks * 16 + (lane & 15);
                int cc = wn + nf * 8;
                ldm_x2t(bh[nf], (uint32_t)__cvta_generic_to_shared(&Bs[0][rr][cc]));
                ldm_x2t(bl[nf], (uint32_t)__cvta_generic_to_shared(&Bs[1][rr][cc]));
            }
            #pragma unroll
            for (int mf = 0; mf < 4; mf++)
                #pragma unroll
                for (int nf = 0; nf < 4; nf++) {
                    mma16816(acc[mf][nf], ah[mf], bh[nf]);
                    mma16816(acc[mf][nf], ah[mf], bl[nf]);
                    mma16816(acc[mf][nf], al[mf], bh[nf]);
                }
        }
        __syncthreads();
    }

    #pragma unroll
    for (int mf = 0; mf < 4; mf++) {
        int r0 = bm + wm + mf * 16 + (lane >> 2);
        #pragma unroll
        for (int nf = 0; nf < 4; nf++) {
            int c = bn + wn + nf * 8 + (lane & 3) * 2;
            if (r0 < M) {
                C[(size_t)r0 * N + c]     = acc[mf][nf][0];
                C[(size_t)r0 * N + c + 1] = acc[mf][nf][1];
            }
            if (r0 + 8 < M) {
                C[(size_t)(r0 + 8) * N + c]     = acc[mf][nf][2];
                C[(size_t)(r0 + 8) * N + c + 1] = acc[mf][nf][3];
            }
        }
    }
}

// ======= fused per-node: scores + online softmax + weighted agg + ELU =======
// One warp per destination node. Lane l owns row elements (i*128 + l*4 .. +3).
__global__ __launch_bounds__(256) void k_attn(const float* __restrict__ att, int n)
{
    int d = blockIdx.x * 8 + threadIdx.y;
    if (d >= n) return;
    int lane = threadIdx.x;
    int beg = g_rowptr[d], end = g_rowptr[d + 1];

    const float4* hdp = (const float4*)(g_h + (size_t)d * HID);
    const float4* ap  = (const float4*)att;
    float4 hd[4], av[4];
    #pragma unroll
    for (int i = 0; i < 4; i++) {
        hd[i] = hdp[i * 32 + lane];
        av[i] = __ldg(&ap[i * 32 + lane]);
    }

    float m = -CUDART_INF_F, den = 0.f;
    float4 acc[4];
    #pragma unroll
    for (int i = 0; i < 4; i++) acc[i] = make_float4(0.f, 0.f, 0.f, 0.f);

    for (int j = beg; j < end; j++) {
        int s = g_csrc[j];
        const float4* hsp = (const float4*)(g_h + (size_t)s * HID);
        float4 hs[4];
        float p = 0.f;
        #pragma unroll
        for (int i = 0; i < 4; i++) {
            float4 a = hd[i];
            float4 b = hsp[i * 32 + lane];
            hs[i] = b;
            float v;
            v = a.x + b.x; v = v > 0.f ? v : 0.2f * v; p = fmaf(v, av[i].x, p);
            v = a.y + b.y; v = v > 0.f ? v : 0.2f * v; p = fmaf(v, av[i].y, p);
            v = a.z + b.z; v = v > 0.f ? v : 0.2f * v; p = fmaf(v, av[i].z, p);
            v = a.w + b.w; v = v > 0.f ? v : 0.2f * v; p = fmaf(v, av[i].w, p);
        }
        #pragma unroll
        for (int o = 16; o; o >>= 1) p += __shfl_xor_sync(0xffffffffu, p, o);

        if (lane == 0) g_w[j] = p;          // raw score, rewritten below

        if (p > m) {
            float scale = expf(m - p);      // m=-inf -> 0, zeroes stale state
            den *= scale;
            #pragma unroll
            for (int i = 0; i < 4; i++) {
                acc[i].x *= scale; acc[i].y *= scale;
                acc[i].z *= scale; acc[i].w *= scale;
            }
            m = p;
        }
        float w = expf(p - m);
        den += w;
        #pragma unroll
        for (int i = 0; i < 4; i++) {
            acc[i].x = fmaf(w, hs[i].x, acc[i].x);
            acc[i].y = fmaf(w, hs[i].y, acc[i].y);
            acc[i].z = fmaf(w, hs[i].z, acc[i].z);
            acc[i].w = fmaf(w, hs[i].w, acc[i].w);
        }
    }

    float4* op = (float4*)(g_h1 + (size_t)d * HID);
    if (end > beg) {
        float inv = 1.f / den;
        #pragma unroll
        for (int i = 0; i < 4; i++) {
            float4 r;
            r.x = acc[i].x * inv; r.x = r.x > 0.f ? r.x : expm1f(r.x);
            r.y = acc[i].y * inv; r.y = r.y > 0.f ? r.y : expm1f(r.y);
            r.z = acc[i].z * inv; r.z = r.z > 0.f ? r.z : expm1f(r.z);
            r.w = acc[i].w * inv; r.w = r.w > 0.f ? r.w : expm1f(r.w);
            op[i * 32 + lane] = r;
        }
        // normalized weights for the second (alpha-tied) aggregation
        for (int j = beg + lane; j < end; j += 32)
            g_w[j] = expf(g_w[j] - m) * inv;
    } else {
        float4 z = make_float4(0.f, 0.f, 0.f, 0.f);
        #pragma unroll
        for (int i = 0; i < 4; i++) op[i * 32 + lane] = z;
    }
}

// ======= second aggregation: h3 = elu(sum_e w_e * g[src_e]) =======
__global__ __launch_bounds__(256) void k_agg2(int n)
{
    int d = blockIdx.x * 8 + threadIdx.y;
    if (d >= n) return;
    int lane = threadIdx.x;
    int beg = g_rowptr[d], end = g_rowptr[d + 1];

    float4 acc[4];
    #pragma unroll
    for (int i = 0; i < 4; i++) acc[i] = make_float4(0.f, 0.f, 0.f, 0.f);

    for (int j = beg; j < end; j++) {
        int s = g_csrc[j];
        float w = g_w[j];
        const float4* gp = (const float4*)(g_gbuf + (size_t)s * HID);
        #pragma unroll
        for (int i = 0; i < 4; i++) {
            float4 v = gp[i * 32 + lane];
            acc[i].x = fmaf(w, v.x, acc[i].x);
            acc[i].y = fmaf(w, v.y, acc[i].y);
            acc[i].z = fmaf(w, v.z, acc[i].z);
            acc[i].w = fmaf(w, v.w, acc[i].w);
        }
    }

    float4* op = (float4*)(g_h3 + (size_t)d * HID);
    #pragma unroll
    for (int i = 0; i < 4; i++) {
        float4 r = acc[i];
        r.x = r.x > 0.f ? r.x : expm1f(r.x);
        r.y = r.y > 0.f ? r.y : expm1f(r.y);
        r.z = r.z > 0.f ? r.z : expm1f(r.z);
        r.w = r.w > 0.f ? r.w : expm1f(r.w);
        op[i * 32 + lane] = r;
    }
}

// ---------------- h2 = h1 @ W2  (K=512, OUT=30), one warp per row ----------------
__global__ void k_h2(const float* __restrict__ h1, const float* __restrict__ W2,
                     float* __restrict__ h2, int n)
{
    int w = blockIdx.x * 8 + threadIdx.y;
    if (w >= n) return;
    int lane = threadIdx.x;
    float acc[DOUT];
    #pragma unroll
    for (int j = 0; j < DOUT; j++) acc[j] = 0.f;
    const float* row = h1 + (size_t)w * HID;
    for (int k = lane; k < HID; k += 32) {
        float hv = row[k];
        const float* w2r = W2 + (size_t)k * DOUT;
        #pragma unroll
        for (int j = 0; j < DOUT; j++) acc[j] = fmaf(hv, __ldg(&w2r[j]), acc[j]);
    }
    #pragma unroll
    for (int j = 0; j < DOUT; j++)
        #pragma unroll
        for (int o = 16; o; o >>= 1) acc[j] += __shfl_xor_sync(0xffffffffu, acc[j], o);
    #pragma unroll
    for (int j = 0; j < DOUT; j++)
        if (lane == j) h2[(size_t)w * DOUT + j] = acc[j];
}

// ---------------- g = h2 @ W2^T  (K=30), one thread per output ----------------
__global__ void k_g(const float* __restrict__ h2, const float* __restrict__ W2, long total) {
    long i = (long)blockIdx.x * 256 + threadIdx.x;
    if (i >= total) return;
    int nrow = (int)(i / HID);
    int c = (int)(i % HID);
    const float* h2r = h2 + (size_t)nrow * DOUT;
    const float* w2r = W2 + (size_t)c * DOUT;
    float s = 0.f;
    #pragma unroll
    for (int j = 0; j < DOUT; j++) s = fmaf(h2r[j], __ldg(&w2r[j]), s);
    g_gbuf[i] = s;
}

// ---------------- launch ----------------
extern "C" void kernel_launch(void* const* d_in, const int* in_sizes, int n_in,
                              void* d_out, int out_size)
{
    const float* features = (const float*)d_in[0];
    const int*   eidx     = (const int*)d_in[1];
    const float* W1       = (const float*)d_in[2];
    const float* att1     = (const float*)d_in[3];
    const float* W2       = (const float*)d_in[4];
    const float* W4       = (const float*)d_in[5];
    float* out = (float*)d_out;

    const int n = in_sizes[0] / DIN;      // 50000
    const int E = in_sizes[1] / 2;        // 300000
    const int* src = eidx;
    const int* dst = eidx + E;

    float* h;   cudaGetSymbolAddress((void**)&h,   g_h);
    float* h1;  cudaGetSymbolAddress((void**)&h1,  g_h1);
    float* h3;  cudaGetSymbolAddress((void**)&h3,  g_h3);

    const long tot = (long)n * HID;
    const dim3 warp8(32, 8);

    // CSR build (dst-sorted adjacency)
    k_zero_cnt<<<(n + 255) / 256, 256>>>(n);
    k_hist<<<(E + 255) / 256, 256>>>(dst, E);
    k_scan<<<1, 1024>>>(n, E);
    k_scatter<<<(E + 255) / 256, 256>>>(src, dst, E);

    // 1) h = X @ W1  (tensor cores, bf16 split)
    {
        dim3 g(HID / 128, (n + 127) / 128);
        k_mma_split<<<g, 256>>>(features, W1, h, n, HID, DIN);
    }

    // 2) fused GATv2: scores + softmax + aggregate + ELU -> h1, weights -> g_w
    k_attn<<<(n + 7) / 8, warp8>>>(att1, n);

    // 3) h2 = h1 @ W2 -> first output chunk [n, 30]
    k_h2<<<(n + 7) / 8, warp8>>>(h1, W2, out, n);

    // 4) g = h2 @ W2^T
    k_g<<<(unsigned)((tot + 255) / 256), 256>>>(out, W2, tot);

    // 5) h3 = elu(aggregate(g, tied alpha))
    k_agg2<<<(n + 7) / 8, warp8>>>(n);

    // 6) h4 = h3 @ W4 -> second output chunk [n, 1024]
    {
        dim3 g(DIN / 128, (n + 127) / 128);
        k_mma_split<<<g, 256>>>(h3, W4, out + (size_t)n * DOUT, n, DIN, HID);
    }
}

// round 5
// speedup vs baseline: 2.0249x; 1.0200x over previous
#include <cuda_runtime.h>
#include <cuda_bf16.h>
#include <math.h>
#include <math_constants.h>
#include <stdint.h>

#define NN   50000
#define EE   300000
#define DIN  1024
#define HID  512
#define DOUT 30

// ---------------- scratch (no allocs allowed) ----------------
__device__ float g_h[(size_t)NN * HID];      // h = X @ W1
__device__ float g_h3[(size_t)NN * HID];     // h3 = elu(agg30 @ W2^T)
__device__ float g_a30[(size_t)NN * DOUT];   // 30-dim aggregation of h2
__device__ int   g_cnt[NN];                  // per-dst degree
__device__ int   g_rowptr[NN + 1];           // CSR row pointers
__device__ int   g_cur[NN];                  // scatter cursors
__device__ int   g_csrc[EE];                 // CSR src node ids
__device__ float g_w[EE];                    // raw score, then normalized weight

// ---------------- CSR build ----------------
__global__ void k_zero_cnt(int n) {
    int i = blockIdx.x * 256 + threadIdx.x;
    if (i < n) g_cnt[i] = 0;
}

__global__ void k_hist(const int* __restrict__ dst, int E) {
    int e = blockIdx.x * 256 + threadIdx.x;
    if (e < E) atomicAdd(&g_cnt[dst[e]], 1);
}

__global__ __launch_bounds__(1024) void k_scan(int n, int E) {
    __shared__ int sums[1024];
    int t = threadIdx.x;
    int chunk = (n + 1023) >> 10;
    int s0 = t * chunk, s1 = min(s0 + chunk, n);
    int local = 0;
    for (int i = s0; i < s1; i++) local += g_cnt[i];
    sums[t] = local;
    __syncthreads();
    #pragma unroll
    for (int off = 1; off < 1024; off <<= 1) {
        int x = (t >= off) ? sums[t - off] : 0;
        __syncthreads();
        sums[t] += x;
        __syncthreads();
    }
    int run = sums[t] - local;   // exclusive prefix
    for (int i = s0; i < s1; i++) {
        int c = g_cnt[i];
        g_rowptr[i] = run;
        g_cur[i] = run;
        run += c;
    }
    if (t == 0) g_rowptr[n] = E;
}

__global__ void k_scatter(const int* __restrict__ src, const int* __restrict__ dst, int E) {
    int e = blockIdx.x * 256 + threadIdx.x;
    if (e >= E) return;
    int pos = atomicAdd(&g_cur[dst[e]], 1);
    g_csrc[pos] = src[e];
}

// ================= tensor-core GEMM: C[M,N] = A[M,K] @ B[K,N] =================
// fp32 in/out, internally bf16 hi/lo split (3 mma products) for ~1e-5 accuracy.

__device__ __forceinline__ void ldm_x4(uint32_t* r, uint32_t addr) {
    asm volatile("ldmatrix.sync.aligned.m8n8.x4.shared.b16 {%0,%1,%2,%3}, [%4];"
        : "=r"(r[0]), "=r"(r[1]), "=r"(r[2]), "=r"(r[3]) : "r"(addr));
}
__device__ __forceinline__ void ldm_x2t(uint32_t* r, uint32_t addr) {
    asm volatile("ldmatrix.sync.aligned.m8n8.x2.trans.shared.b16 {%0,%1}, [%2];"
        : "=r"(r[0]), "=r"(r[1]) : "r"(addr));
}
__device__ __forceinline__ void mma16816(float* c, const uint32_t* a, const uint32_t* b) {
    asm volatile("mma.sync.aligned.m16n8k16.row.col.f32.bf16.bf16.f32 "
        "{%0,%1,%2,%3}, {%4,%5,%6,%7}, {%8,%9}, {%0,%1,%2,%3};"
        : "+f"(c[0]), "+f"(c[1]), "+f"(c[2]), "+f"(c[3])
        : "r"(a[0]), "r"(a[1]), "r"(a[2]), "r"(a[3]), "r"(b[0]), "r"(b[1]));
}
__device__ __forceinline__ void split2(float x, __nv_bfloat16& h, __nv_bfloat16& l) {
    h = __float2bfloat16(x);
    l = __float2bfloat16(x - __bfloat162float(h));
}

#define APAD 8
#define BPAD 8

__global__ __launch_bounds__(256) void k_mma_split(
    const float* __restrict__ A, const float* __restrict__ B,
    float* __restrict__ C, int M, int N, int K)
{
    __shared__ __nv_bfloat16 As[2][128][32 + APAD];
    __shared__ __nv_bfloat16 Bs[2][32][128 + BPAD];

    const int tid  = threadIdx.x;
    const int lane = tid & 31;
    const int wid  = tid >> 5;
    const int wm   = (wid & 1) * 64;
    const int wn   = (wid >> 1) * 32;
    const int bm   = blockIdx.y * 128;
    const int bn   = blockIdx.x * 128;

    float acc[4][4][4] = {};

    for (int k0 = 0; k0 < K; k0 += 32) {
        #pragma unroll
        for (int i = 0; i < 4; i++) {
            int idx = tid + i * 256;
            int r  = idx >> 3;
            int c4 = (idx & 7) * 4;
            float4 v = make_float4(0.f, 0.f, 0.f, 0.f);
            if (bm + r < M) v = *(const float4*)(A + (size_t)(bm + r) * K + k0 + c4);
            union { __nv_bfloat16 b[4]; uint2 u; } ph, pl;
            split2(v.x, ph.b[0], pl.b[0]); split2(v.y, ph.b[1], pl.b[1]);
            split2(v.z, ph.b[2], pl.b[2]); split2(v.w, ph.b[3], pl.b[3]);
            *(uint2*)&As[0][r][c4] = ph.u;
            *(uint2*)&As[1][r][c4] = pl.u;
        }
        #pragma unroll
        for (int i = 0; i < 4; i++) {
            int idx = tid + i * 256;
            int r  = idx >> 5;
            int c4 = (idx & 31) * 4;
            float4 v = *(const float4*)(B + (size_t)(k0 + r) * N + bn + c4);
            union { __nv_bfloat16 b[4]; uint2 u; } ph, pl;
            split2(v.x, ph.b[0], pl.b[0]); split2(v.y, ph.b[1], pl.b[1]);
            split2(v.z, ph.b[2], pl.b[2]); split2(v.w, ph.b[3], pl.b[3]);
            *(uint2*)&Bs[0][r][c4] = ph.u;
            *(uint2*)&Bs[1][r][c4] = pl.u;
        }
        __syncthreads();

        #pragma unroll
        for (int ks = 0; ks < 2; ks++) {
            uint32_t ah[4][4], al[4][4], bh[4][2], bl[4][2];
            #pragma unroll
            for (int mf = 0; mf < 4; mf++) {
                int rr = wm + mf * 16 + (lane & 15);
                int cc = ks * 16 + (lane >> 4) * 8;
                ldm_x4(ah[mf], (uint32_t)__cvta_generic_to_shared(&As[0][rr][cc]));
                ldm_x4(al[mf], (uint32_t)__cvta_generic_to_shared(&As[1][rr][cc]));
            }
            #pragma unroll
            for (int nf = 0; nf < 4; nf++) {
                int rr = ks * 16 + (lane & 15);
                int cc = wn + nf * 8;
                ldm_x2t(bh[nf], (uint32_t)__cvta_generic_to_shared(&Bs[0][rr][cc]));
                ldm_x2t(bl[nf], (uint32_t)__cvta_generic_to_shared(&Bs[1][rr][cc]));
            }
            #pragma unroll
            for (int mf = 0; mf < 4; mf++)
                #pragma unroll
                for (int nf = 0; nf < 4; nf++) {
                    mma16816(acc[mf][nf], ah[mf], bh[nf]);
                    mma16816(acc[mf][nf], ah[mf], bl[nf]);
                    mma16816(acc[mf][nf], al[mf], bh[nf]);
                }
        }
        __syncthreads();
    }

    #pragma unroll
    for (int mf = 0; mf < 4; mf++) {
        int r0 = bm + wm + mf * 16 + (lane >> 2);
        #pragma unroll
        for (int nf = 0; nf < 4; nf++) {
            int c = bn + wn + nf * 8 + (lane & 3) * 2;
            if (r0 < M) {
                C[(size_t)r0 * N + c]     = acc[mf][nf][0];
                C[(size_t)r0 * N + c + 1] = acc[mf][nf][1];
            }
            if (r0 + 8 < M) {
                C[(size_t)(r0 + 8) * N + c]     = acc[mf][nf][2];
                C[(size_t)(r0 + 8) * N + c + 1] = acc[mf][nf][3];
            }
        }
    }
}

// ======= fused per-node: scores + online softmax + agg + ELU + (@W2) =======
// One warp per destination node. Lane l owns row elements (i*128 + l*4 .. +3).
// Writes h2 = elu(agg) @ W2 directly (h1 never materialized) and the
// normalized attention weights (for the tied second aggregation).
__global__ __launch_bounds__(256) void k_attn(const float* __restrict__ att,
                                              const float* __restrict__ W2,
                                              float* __restrict__ h2, int n)
{
    int d = blockIdx.x * 8 + threadIdx.y;
    if (d >= n) return;
    int lane = threadIdx.x;
    int beg = g_rowptr[d], end = g_rowptr[d + 1];

    const float4* hdp = (const float4*)(g_h + (size_t)d * HID);
    const float4* ap  = (const float4*)att;
    float4 hd[4], av[4];
    #pragma unroll
    for (int i = 0; i < 4; i++) {
        hd[i] = hdp[i * 32 + lane];
        av[i] = __ldg(&ap[i * 32 + lane]);
    }

    float m = -CUDART_INF_F, den = 0.f;
    float4 acc[4];
    #pragma unroll
    for (int i = 0; i < 4; i++) acc[i] = make_float4(0.f, 0.f, 0.f, 0.f);

    for (int j = beg; j < end; j++) {
        int s = g_csrc[j];
        const float4* hsp = (const float4*)(g_h + (size_t)s * HID);
        float4 hs[4];
        float p = 0.f;
        #pragma unroll
        for (int i = 0; i < 4; i++) {
            float4 a = hd[i];
            float4 b = hsp[i * 32 + lane];
            hs[i] = b;
            float v;
            v = a.x + b.x; v = v > 0.f ? v : 0.2f * v; p = fmaf(v, av[i].x, p);
            v = a.y + b.y; v = v > 0.f ? v : 0.2f * v; p = fmaf(v, av[i].y, p);
            v = a.z + b.z; v = v > 0.f ? v : 0.2f * v; p = fmaf(v, av[i].z, p);
            v = a.w + b.w; v = v > 0.f ? v : 0.2f * v; p = fmaf(v, av[i].w, p);
        }
        #pragma unroll
        for (int o = 16; o; o >>= 1) p += __shfl_xor_sync(0xffffffffu, p, o);

        if (lane == 0) g_w[j] = p;          // raw score, rewritten below

        if (p > m) {
            float scale = expf(m - p);      // m=-inf -> 0, zeroes stale state
            den *= scale;
            #pragma unroll
            for (int i = 0; i < 4; i++) {
                acc[i].x *= scale; acc[i].y *= scale;
                acc[i].z *= scale; acc[i].w *= scale;
            }
            m = p;
        }
        float w = expf(p - m);
        den += w;
        #pragma unroll
        for (int i = 0; i < 4; i++) {
            acc[i].x = fmaf(w, hs[i].x, acc[i].x);
            acc[i].y = fmaf(w, hs[i].y, acc[i].y);
            acc[i].z = fmaf(w, hs[i].z, acc[i].z);
            acc[i].w = fmaf(w, hs[i].w, acc[i].w);
        }
    }

    // ---- epilogue: h1row (regs) = elu(acc/den); h2row = h1row @ W2 ----
    float h2acc[DOUT];
    #pragma unroll
    for (int j = 0; j < DOUT; j++) h2acc[j] = 0.f;

    if (end > beg) {
        float inv = 1.f / den;
        #pragma unroll
        for (int i = 0; i < 4; i++) {
            float hv[4];
            hv[0] = acc[i].x * inv; hv[0] = hv[0] > 0.f ? hv[0] : expm1f(hv[0]);
            hv[1] = acc[i].y * inv; hv[1] = hv[1] > 0.f ? hv[1] : expm1f(hv[1]);
            hv[2] = acc[i].z * inv; hv[2] = hv[2] > 0.f ? hv[2] : expm1f(hv[2]);
            hv[3] = acc[i].w * inv; hv[3] = hv[3] > 0.f ? hv[3] : expm1f(hv[3]);
            #pragma unroll
            for (int c = 0; c < 4; c++) {
                const float* w2r = W2 + (size_t)(i * 128 + lane * 4 + c) * DOUT;
                float x = hv[c];
                #pragma unroll
                for (int j = 0; j < DOUT; j++)
                    h2acc[j] = fmaf(x, __ldg(&w2r[j]), h2acc[j]);
            }
        }
        // normalized weights for the second (alpha-tied) aggregation
        for (int j = beg + lane; j < end; j += 32)
            g_w[j] = expf(g_w[j] - m) * inv;
    }

    #pragma unroll
    for (int j = 0; j < DOUT; j++)
        #pragma unroll
        for (int o = 16; o; o >>= 1)
            h2acc[j] += __shfl_xor_sync(0xffffffffu, h2acc[j], o);
    #pragma unroll
    for (int j = 0; j < DOUT; j++)
        if (lane == j) h2[(size_t)d * DOUT + j] = h2acc[j];
}

// ======= 30-dim aggregation: a30[d] = sum_e w_e * h2[src_e]  =======
// (algebraically: aggregate BEFORE expanding with W2^T — linearity)
__global__ __launch_bounds__(256) void k_agg30(const float* __restrict__ h2, int n)
{
    int d = blockIdx.x * 8 + threadIdx.y;
    if (d >= n) return;
    int lane = threadIdx.x;
    int beg = g_rowptr[d], end = g_rowptr[d + 1];

    float a = 0.f;
    for (int j = beg; j < end; j++) {
        int s = g_csrc[j];
        float w = g_w[j];
        if (lane < DOUT) a = fmaf(w, h2[(size_t)s * DOUT + lane], a);
    }
    if (lane < DOUT) g_a30[(size_t)d * DOUT + lane] = a;
}

// ======= expand: h3 = elu(a30 @ W2^T)  (K=30) =======
__global__ void k_expand(const float* __restrict__ W2, long total) {
    long i = (long)blockIdx.x * 256 + threadIdx.x;
    if (i >= total) return;
    int nrow = (int)(i / HID);
    int c = (int)(i % HID);
    const float* ar  = g_a30 + (size_t)nrow * DOUT;
    const float* w2r = W2 + (size_t)c * DOUT;
    float s = 0.f;
    #pragma unroll
    for (int j = 0; j < DOUT; j++) s = fmaf(ar[j], __ldg(&w2r[j]), s);
    g_h3[i] = s > 0.f ? s : expm1f(s);
}

// ---------------- launch ----------------
extern "C" void kernel_launch(void* const* d_in, const int* in_sizes, int n_in,
                              void* d_out, int out_size)
{
    const float* features = (const float*)d_in[0];
    const int*   eidx     = (const int*)d_in[1];
    const float* W1       = (const float*)d_in[2];
    const float* att1     = (const float*)d_in[3];
    const float* W2       = (const float*)d_in[4];
    const float* W4       = (const float*)d_in[5];
    float* out = (float*)d_out;

    const int n = in_sizes[0] / DIN;      // 50000
    const int E = in_sizes[1] / 2;        // 300000
    const int* src = eidx;
    const int* dst = eidx + E;

    float* h;   cudaGetSymbolAddress((void**)&h,   g_h);
    float* h3;  cudaGetSymbolAddress((void**)&h3,  g_h3);

    const long tot = (long)n * HID;
    const dim3 warp8(32, 8);

    // CSR build (dst-sorted adjacency)
    k_zero_cnt<<<(n + 255) / 256, 256>>>(n);
    k_hist<<<(E + 255) / 256, 256>>>(dst, E);
    k_scan<<<1, 1024>>>(n, E);
    k_scatter<<<(E + 255) / 256, 256>>>(src, dst, E);

    // 1) h = X @ W1  (tensor cores, bf16 split)
    {
        dim3 g(HID / 128, (n + 127) / 128);
        k_mma_split<<<g, 256>>>(features, W1, h, n, HID, DIN);
    }

    // 2) fused GATv2 + h2 projection -> out[0 : n*30], weights -> g_w
    k_attn<<<(n + 7) / 8, warp8>>>(att1, W2, out, n);

    // 3) 30-dim tied-alpha aggregation of h2
    k_agg30<<<(n + 7) / 8, warp8>>>(out, n);

    // 4) h3 = elu(a30 @ W2^T)
    k_expand<<<(unsigned)((tot + 255) / 256), 256>>>(W2, tot);

    // 5) h4 = h3 @ W4 -> second output chunk [n, 1024]
    {
        dim3 g(DIN / 128, (n + 127) / 128);
        k_mma_split<<<g, 256>>>(h3, W4, out + (size_t)n * DOUT, n, DIN, HID);
    }
}